// round 11
// baseline (speedup 1.0000x reference)
#include <cuda_runtime.h>
#include <cuda_fp16.h>
#include <cstdint>

#define L_SEQ 1024
#define BATCH_BS 8
#define EMB 512
#define O3 1536
#define NB 64            // BATCH_BS * NH
#define BSPLIT 16        // batches per split (4 splits): E buffer stays in L2

// Q pre-scale: exp(0.125*s) = exp2(s * 0.125 * log2(e))
#define QSCALE 0.18033688011112042f

// Scratch (device globals)
__device__ __half g_Ah[(size_t)8192 * EMB];       // emb as fp16, 8 MB
__device__ __half g_Bh[(size_t)O3 * EMB];         // W_qkv as fp16, 1.5 MB
__device__ __half g_Q[(size_t)NB * L_SEQ * 64];   // 8 MB (pre-scaled by QSCALE)
__device__ __half g_K[(size_t)NB * L_SEQ * 64];   // 8 MB
__device__ float  g_V[(size_t)NB * L_SEQ * 64];   // 16 MB
__device__ __half g_E[(size_t)BSPLIT * L_SEQ * L_SEQ]; // 33.5 MB, L2-resident, reused
__device__ float  g_Z[NB * L_SEQ];                // raw row sums (atomic)
__device__ float  g_W[NB * L_SEQ];                // attn weights (direct store)
__device__ float  g_P[NB * 8 * 64];               // k4a partials

// ---------------------------------------------------------------------------
// helpers
// ---------------------------------------------------------------------------
__device__ __forceinline__ uint32_t f22h2(float lo, float hi) {
    __half2 h = __floats2half2_rn(lo, hi);
    return reinterpret_cast<uint32_t&>(h);
}
__device__ __forceinline__ uint32_t smem_u32(const void* p) {
    return (uint32_t)__cvta_generic_to_shared(p);
}
__device__ __forceinline__ float frcp(float x) {
    float r;
    asm("rcp.approx.f32 %0, %1;" : "=f"(r) : "f"(x));
    return r;
}
__device__ __forceinline__ float fex2(float x) {
    float r;
    asm("ex2.approx.f32 %0, %1;" : "=f"(r) : "f"(x));
    return r;
}
__device__ __forceinline__ void ldsm4(uint32_t& r0, uint32_t& r1,
                                      uint32_t& r2, uint32_t& r3,
                                      const __half* p) {
    uint32_t addr = smem_u32(p);
    asm volatile("ldmatrix.sync.aligned.m8n8.x4.shared.b16 {%0,%1,%2,%3}, [%4];"
                 : "=r"(r0), "=r"(r1), "=r"(r2), "=r"(r3) : "r"(addr));
}
__device__ __forceinline__ void mma_f16(float* d, const uint32_t* a, const uint32_t* b) {
    asm volatile(
        "mma.sync.aligned.m16n8k16.row.col.f32.f16.f16.f32 "
        "{%0,%1,%2,%3}, {%4,%5,%6,%7}, {%8,%9}, {%0,%1,%2,%3};\n"
        : "+f"(d[0]), "+f"(d[1]), "+f"(d[2]), "+f"(d[3])
        : "r"(a[0]), "r"(a[1]), "r"(a[2]), "r"(a[3]), "r"(b[0]), "r"(b[1]));
}

// ---------------------------------------------------------------------------
// KC: one-time fp32 -> fp16 convert of emb + W_qkv; zero Z.
// ---------------------------------------------------------------------------
__global__ void __launch_bounds__(1024) kcvt(
    const float* __restrict__ A, const float* __restrict__ B)
{
    const size_t i = (size_t)blockIdx.x * 1024 + threadIdx.x;
    if (i < 1048576) {
        const float4 v = ((const float4*)A)[i];
        ((uint2*)g_Ah)[i] = make_uint2(f22h2(v.x, v.y), f22h2(v.z, v.w));
    } else {
        const size_t j = i - 1048576;
        const float4 v = ((const float4*)B)[j];
        ((uint2*)g_Bh)[j] = make_uint2(f22h2(v.x, v.y), f22h2(v.z, v.w));
    }
    if (i < NB * L_SEQ)
        g_Z[i] = 0.0f;
}

// ---------------------------------------------------------------------------
// K1: C = emb_h[8192,512] @ W_h[1536,512]^T + bias  (fp16 mma, NT)
// double-buffered smem, one sync per k-stage. Q stored pre-scaled by QSCALE.
// ---------------------------------------------------------------------------
#define SA 40
__global__ void __launch_bounds__(256) k1_qkv(const float* __restrict__ bias)
{
    __shared__ __half As[2][128 * SA];
    __shared__ __half Bs[2][128 * SA];

    const int tid  = threadIdx.x;
    const int warp = tid >> 5;
    const int lane = tid & 31;
    const int g = lane >> 2, t = lane & 3;
    const int wm0 = (warp >> 2) * 64;
    const int wn0 = (warp & 3) * 32;
    const int m0 = blockIdx.y * 128;
    const int n0 = blockIdx.x * 128;

    const int lrow = tid >> 1;
    const int lk   = (tid & 1) * 16;
    const __half* ap = g_Ah + (size_t)(m0 + lrow) * EMB + lk;
    const __half* bp = g_Bh + (size_t)(n0 + lrow) * EMB + lk;

    const int lm = lane & 15;
    const int lc = (lane >> 4) * 8;

    float acc[4][4][4];
#pragma unroll
    for (int i = 0; i < 4; i++)
#pragma unroll
        for (int j = 0; j < 4; j++)
#pragma unroll
            for (int c = 0; c < 4; c++) acc[i][j][c] = 0.0f;

    uint4 a0 = *(const uint4*)(ap);
    uint4 a1 = *(const uint4*)(ap + 8);
    uint4 b0 = *(const uint4*)(bp);
    uint4 b1 = *(const uint4*)(bp + 8);
    *(uint4*)(As[0] + lrow * SA + lk)     = a0;
    *(uint4*)(As[0] + lrow * SA + lk + 8) = a1;
    *(uint4*)(Bs[0] + lrow * SA + lk)     = b0;
    *(uint4*)(Bs[0] + lrow * SA + lk + 8) = b1;

#pragma unroll 4
    for (int s = 0; s < 16; s++) {
        if (s < 15) {
            const int nk = (s + 1) * 32;
            a0 = *(const uint4*)(ap + nk);
            a1 = *(const uint4*)(ap + nk + 8);
            b0 = *(const uint4*)(bp + nk);
            b1 = *(const uint4*)(bp + nk + 8);
        }
        __syncthreads();
        const __half* Ab = As[s & 1];
        const __half* Bb = Bs[s & 1];
#pragma unroll
        for (int kk = 0; kk < 32; kk += 16) {
            uint32_t af[4][4];
#pragma unroll
            for (int im = 0; im < 4; im++)
                ldsm4(af[im][0], af[im][1], af[im][2], af[im][3],
                      Ab + (wm0 + im * 16 + lm) * SA + kk + lc);
            uint32_t br0[4], br1[4];
            ldsm4(br0[0], br0[1], br0[2], br0[3], Bb + (wn0 +      lm) * SA + kk + lc);
            ldsm4(br1[0], br1[1], br1[2], br1[3], Bb + (wn0 + 16 + lm) * SA + kk + lc);
            uint32_t bf[4][2] = {{br0[0], br0[2]}, {br0[1], br0[3]},
                                 {br1[0], br1[2]}, {br1[1], br1[3]}};
#pragma unroll
            for (int im = 0; im < 4; im++)
#pragma unroll
                for (int in = 0; in < 4; in++)
                    mma_f16(acc[im][in], af[im], bf[in]);
        }
        if (s < 15) {
            __half* An = As[(s + 1) & 1];
            __half* Bn = Bs[(s + 1) & 1];
            *(uint4*)(An + lrow * SA + lk)     = a0;
            *(uint4*)(An + lrow * SA + lk + 8) = a1;
            *(uint4*)(Bn + lrow * SA + lk)     = b0;
            *(uint4*)(Bn + lrow * SA + lk + 8) = b1;
        }
    }

#pragma unroll
    for (int im = 0; im < 4; im++) {
        const int r0 = m0 + wm0 + im * 16 + g;
#pragma unroll
        for (int in = 0; in < 4; in++) {
            const int c   = n0 + wn0 + in * 8 + 2 * t;
            const int h   = c / 192;
            const int rem = c - h * 192;
            const int sect = rem >> 6;
            const int d    = rem & 63;
            const float b0f = __ldg(bias + c), b1f = __ldg(bias + c + 1);
#pragma unroll
            for (int hf = 0; hf < 2; hf++) {
                const int r = r0 + hf * 8;
                const int l = r >> 3, bb = r & 7;
                const size_t off = ((size_t)(bb * 8 + h) << 16) + l * 64 + d;
                const float v0 = acc[im][in][2 * hf    ] + b0f;
                const float v1 = acc[im][in][2 * hf + 1] + b1f;
                if (sect == 0) {
                    *(uint32_t*)(g_Q + off) = f22h2(v0 * QSCALE, v1 * QSCALE);
                } else if (sect == 1) {
                    *(uint32_t*)(g_K + off) = f22h2(v0, v1);
                } else {
                    *(float2*)(g_V + off) = make_float2(v0, v1);
                }
            }
        }
    }
}

// ---------------------------------------------------------------------------
// K2E: S (log2 domain) = Qs @ K^T, tile 128x128, per (B, m0t, n0t) in a
// BSPLIT-batch window. E = exp2(S) -> smem stage -> coalesced store into the
// L2-resident g_E chunk. Row-sum partials -> g_Z (smem-combined atomics).
// E tile layout: ((Bloc*8 + m0t)*8 + n0t)*16384, row-major 128x128.
// ---------------------------------------------------------------------------
#define SQ 72
#define SE 136
__global__ void __launch_bounds__(256) k2e_scores(int Boff)
{
    __shared__ __half sbuf[2 * 128 * SQ];   // Qs | Ks, reused as E staging
    __shared__ float  zsh[128];

    __half* Qs = sbuf;
    __half* Ks = sbuf + 128 * SQ;
    __half* Ssm = sbuf;

    const int tid  = threadIdx.x;
    const int warp = tid >> 5;
    const int lane = tid & 31;
    const int g = lane >> 2, t = lane & 3;
    const int wm0 = (warp >> 2) * 64;
    const int wn0 = (warp & 3) * 32;

    const int Bloc = blockIdx.z;
    const int B    = Boff + Bloc;
    const int n0t = blockIdx.x;
    const int m0t = blockIdx.y;
    const int n0  = n0t * 128;
    const int m0  = m0t * 128;

    if (tid < 128) zsh[tid] = 0.0f;

    const __half* qg = g_Q + ((size_t)B << 16) + (size_t)m0 * 64;
    const __half* kg = g_K + ((size_t)B << 16) + (size_t)n0 * 64;
#pragma unroll
    for (int j = 0; j < 4; j++) {
        const int idx = tid + j * 256;
        const int row = idx >> 3;
        const int ch  = (idx & 7) * 8;
        *(uint4*)(Qs + row * SQ + ch) = *(const uint4*)(qg + row * 64 + ch);
        *(uint4*)(Ks + row * SQ + ch) = *(const uint4*)(kg + row * 64 + ch);
    }
    __syncthreads();

    const int lm = lane & 15;
    const int lc = (lane >> 4) * 8;

    float acc[4][4][4];
#pragma unroll
    for (int i = 0; i < 4; i++)
#pragma unroll
        for (int j = 0; j < 4; j++)
#pragma unroll
            for (int c = 0; c < 4; c++) acc[i][j][c] = 0.0f;

#pragma unroll
    for (int kk = 0; kk < 64; kk += 16) {
        uint32_t af[4][4];
#pragma unroll
        for (int im = 0; im < 4; im++)
            ldsm4(af[im][0], af[im][1], af[im][2], af[im][3],
                  Qs + (wm0 + im * 16 + lm) * SQ + kk + lc);
        uint32_t br0[4], br1[4];
        ldsm4(br0[0], br0[1], br0[2], br0[3], Ks + (wn0 +      lm) * SQ + kk + lc);
        ldsm4(br1[0], br1[1], br1[2], br1[3], Ks + (wn0 + 16 + lm) * SQ + kk + lc);
        uint32_t bf[4][2] = {{br0[0], br0[2]}, {br0[1], br0[3]},
                             {br1[0], br1[2]}, {br1[1], br1[3]}};
#pragma unroll
        for (int im = 0; im < 4; im++)
#pragma unroll
            for (int in = 0; in < 4; in++)
                mma_f16(acc[im][in], af[im], bf[in]);
    }

    __syncthreads();   // Qs/Ks reads done; reuse as E staging

#pragma unroll
    for (int im = 0; im < 4; im++) {
#pragma unroll
        for (int hf = 0; hf < 2; hf++) {
            const int rloc = wm0 + im * 16 + g + hf * 8;
            float rp = 0.0f;
#pragma unroll
            for (int in = 0; in < 4; in++) {
                const float e0 = fex2(acc[im][in][2 * hf    ]);
                const float e1 = fex2(acc[im][in][2 * hf + 1]);
                rp += e0 + e1;
                *(uint32_t*)(Ssm + rloc * SE + wn0 + in * 8 + 2 * t) = f22h2(e0, e1);
            }
            rp += __shfl_xor_sync(0xffffffffu, rp, 1);
            rp += __shfl_xor_sync(0xffffffffu, rp, 2);
            if (t == 0)
                atomicAdd(&zsh[rloc], rp);
        }
    }
    __syncthreads();

    if (tid < 128)
        atomicAdd(&g_Z[B * 1024 + m0 + tid], zsh[tid]);

    __half* eg = g_E + ((((size_t)Bloc * 8 + m0t) * 8) + n0t) * 16384;
#pragma unroll
    for (int it = 0; it < 8; it++) {
        const int idx = tid + it * 256;
        const int row = idx >> 4;
        const int co  = (idx & 15) * 8;
        *(uint4*)(eg + row * 128 + co) = *(const uint4*)(Ssm + row * SE + co);
    }
}

// ---------------------------------------------------------------------------
// K3: W[B][n0t*128 + c] = sum over 1024 rows of E * rcp(Z[row]).
// E read hits L2 (buffer written by the immediately preceding k2e).
// grid (8 n0t, BSPLIT), 256 thr = 64 colpairs x 4 rowgroups. Direct store.
// ---------------------------------------------------------------------------
__global__ void __launch_bounds__(256) k3_colsum(int Boff)
{
    __shared__ float  Rs[1024];
    __shared__ float2 sh[256];

    const int Bloc = blockIdx.y;
    const int B    = Boff + Bloc;
    const int n0t  = blockIdx.x;
    const int tid  = threadIdx.x;

    for (int i = tid; i < 1024; i += 256)
        Rs[i] = frcp(g_Z[B * 1024 + i]);
    __syncthreads();

    const int cp = tid & 63;
    const int rg = tid >> 6;

    float a0 = 0.0f, a1 = 0.0f;
#pragma unroll
    for (int mt = 0; mt < 8; mt++) {
        const __half* ep = g_E + ((((size_t)Bloc * 8 + mt) * 8) + n0t) * 16384
                         + (rg * 32) * 128 + cp * 2;
        const float* rr = Rs + mt * 128 + rg * 32;
#pragma unroll 8
        for (int r = 0; r < 32; r++) {
            const float2 e = __half22float2(*(const __half2*)(ep + r * 128));
            const float rv = rr[r];
            a0 = fmaf(e.x, rv, a0);
            a1 = fmaf(e.y, rv, a1);
        }
    }

    sh[tid] = make_float2(a0, a1);
    __syncthreads();
    if (tid < 64) {
        float2 s = sh[tid];
#pragma unroll
        for (int gq = 1; gq < 4; gq++) {
            s.x += sh[gq * 64 + tid].x;
            s.y += sh[gq * 64 + tid].y;
        }
        *(float2*)(g_W + B * 1024 + n0t * 128 + tid * 2) = s;
    }
}

// ---------------------------------------------------------------------------
// K4a: partial dot products. grid (8 chunks, 64 B), block 256.
// ---------------------------------------------------------------------------
__global__ void __launch_bounds__(256) k4a_partial()
{
    const int B  = blockIdx.y;
    const int ch = blockIdx.x;
    const int tid = threadIdx.x;
    const int d = tid & 63, mg = tid >> 6;

    const float* vptr = g_V + ((size_t)B << 16) + (size_t)ch * 128 * 64 + d;
    const float* wp   = g_W + B * 1024 + ch * 128;

    float acc = 0.0f;
#pragma unroll 8
    for (int m = mg; m < 128; m += 4)
        acc = fmaf(wp[m], vptr[m * 64], acc);

    __shared__ float sh[4][64];
    sh[mg][d] = acc;
    __syncthreads();
    if (tid < 64)
        g_P[(B * 8 + ch) * 64 + tid] =
            sh[0][tid] + sh[1][tid] + sh[2][tid] + sh[3][tid];
}

// ---------------------------------------------------------------------------
// K4b: reduce 8 partials + GroupNorm + affine + out. grid 64, block 64.
// ---------------------------------------------------------------------------
__global__ void __launch_bounds__(64) k4b_gn(
    const float* __restrict__ gw, const float* __restrict__ gb,
    float* __restrict__ out)
{
    const int B  = blockIdx.x;
    const int bb = B >> 3, hh = B & 7;
    const int tid = threadIdx.x;
    const int lane = tid & 31, wp = tid >> 5;

    float v = 0.0f;
#pragma unroll
    for (int c = 0; c < 8; c++)
        v += g_P[(B * 8 + c) * 64 + tid];

    float s = v, sq = v * v;
#pragma unroll
    for (int o = 16; o > 0; o >>= 1) {
        s  += __shfl_xor_sync(0xffffffffu, s, o);
        sq += __shfl_xor_sync(0xffffffffu, sq, o);
    }
    __shared__ float red[4];
    if (lane == 0) { red[wp * 2] = s; red[wp * 2 + 1] = sq; }
    __syncthreads();
    const float sum = red[0] + red[2];
    const float ssq = red[1] + red[3];
    const float mean = sum * (1.0f / 64.0f);
    const float var  = ssq * (1.0f / 64.0f) - mean * mean;
    out[bb * 512 + hh * 64 + tid] =
        (v - mean) * rsqrtf(var + 1e-5f) * __ldg(gw + hh) + __ldg(gb + hh);
}

// ---------------------------------------------------------------------------
// Launcher (graph-capturable)
// ---------------------------------------------------------------------------
extern "C" void kernel_launch(void* const* d_in, const int* in_sizes, int n_in,
                              void* d_out, int out_size)
{
    (void)in_sizes; (void)n_in; (void)out_size;
    const float* emb = (const float*)d_in[0];
    const float* Wq  = (const float*)d_in[1];
    const float* bq  = (const float*)d_in[2];
    const float* gw  = (const float*)d_in[3];
    const float* gb  = (const float*)d_in[4];
    float* out = (float*)d_out;

    kcvt   <<<1216, 1024>>>(emb, Wq);
    k1_qkv <<<dim3(12, 64), 256>>>(bq);
    for (int s = 0; s < NB / BSPLIT; s++) {
        k2e_scores<<<dim3(8, 8, BSPLIT), 256>>>(s * BSPLIT);
        k3_colsum <<<dim3(8, BSPLIT), 256>>>(s * BSPLIT);
    }
    k4a_partial<<<dim3(8, 64), 256>>>();
    k4b_gn <<<64, 64>>>(gw, gb, out);
}

// round 12
// speedup vs baseline: 1.2547x; 1.2547x over previous
#include <cuda_runtime.h>
#include <cuda_fp16.h>
#include <cstdint>

#define L_SEQ 1024
#define BATCH_BS 8
#define EMB 512
#define O3 1536
#define NB 64            // BATCH_BS * NH

// Q pre-scale: exp(0.125*s) = exp2(s * 0.125 * log2(e))
#define QSCALE 0.18033688011112042f

// Scratch (device globals)
__device__ __half g_Ah[(size_t)8192 * EMB];       // emb as fp16, 8 MB
__device__ __half g_Bh[(size_t)O3 * EMB];         // W_qkv as fp16, 1.5 MB
__device__ __half g_Q[(size_t)NB * L_SEQ * 64];   // 8 MB (pre-scaled by QSCALE)
__device__ __half g_K[(size_t)NB * L_SEQ * 64];   // 8 MB
__device__ float  g_V[(size_t)NB * L_SEQ * 64];   // 16 MB
__device__ float  g_Z[NB * L_SEQ];                // raw row sums (atomic)
__device__ float  g_W[NB * L_SEQ];                // attn weights (atomic)
__device__ float  g_P[NB * 8 * 64];               // k4a partials

// ---------------------------------------------------------------------------
// helpers
// ---------------------------------------------------------------------------
__device__ __forceinline__ uint32_t f22h2(float lo, float hi) {
    __half2 h = __floats2half2_rn(lo, hi);
    return reinterpret_cast<uint32_t&>(h);
}
__device__ __forceinline__ uint32_t smem_u32(const void* p) {
    return (uint32_t)__cvta_generic_to_shared(p);
}
__device__ __forceinline__ float frcp(float x) {
    float r;
    asm("rcp.approx.f32 %0, %1;" : "=f"(r) : "f"(x));
    return r;
}
// paired exp2 in fp16: ONE MUFU op for TWO exponentials
__device__ __forceinline__ float2 ex2_pair(float a, float b) {
    uint32_t p = f22h2(a, b);
    uint32_t e;
    asm("ex2.approx.f16x2 %0, %1;" : "=r"(e) : "r"(p));
    __half2 eh = *reinterpret_cast<__half2*>(&e);
    return __half22float2(eh);
}
__device__ __forceinline__ void ldsm4(uint32_t& r0, uint32_t& r1,
                                      uint32_t& r2, uint32_t& r3,
                                      const __half* p) {
    uint32_t addr = smem_u32(p);
    asm volatile("ldmatrix.sync.aligned.m8n8.x4.shared.b16 {%0,%1,%2,%3}, [%4];"
                 : "=r"(r0), "=r"(r1), "=r"(r2), "=r"(r3) : "r"(addr));
}
__device__ __forceinline__ void mma_f16(float* d, const uint32_t* a, const uint32_t* b) {
    asm volatile(
        "mma.sync.aligned.m16n8k16.row.col.f32.f16.f16.f32 "
        "{%0,%1,%2,%3}, {%4,%5,%6,%7}, {%8,%9}, {%0,%1,%2,%3};\n"
        : "+f"(d[0]), "+f"(d[1]), "+f"(d[2]), "+f"(d[3])
        : "r"(a[0]), "r"(a[1]), "r"(a[2]), "r"(a[3]), "r"(b[0]), "r"(b[1]));
}

// ---------------------------------------------------------------------------
// KC: one-time fp32 -> fp16 convert of emb + W_qkv; zero Z and W.
// ---------------------------------------------------------------------------
__global__ void __launch_bounds__(1024) kcvt(
    const float* __restrict__ A, const float* __restrict__ B)
{
    const size_t i = (size_t)blockIdx.x * 1024 + threadIdx.x;
    if (i < 1048576) {
        const float4 v = ((const float4*)A)[i];
        ((uint2*)g_Ah)[i] = make_uint2(f22h2(v.x, v.y), f22h2(v.z, v.w));
    } else {
        const size_t j = i - 1048576;
        const float4 v = ((const float4*)B)[j];
        ((uint2*)g_Bh)[j] = make_uint2(f22h2(v.x, v.y), f22h2(v.z, v.w));
    }
    if (i < NB * L_SEQ) {
        g_Z[i] = 0.0f;
        g_W[i] = 0.0f;
    }
}

// ---------------------------------------------------------------------------
// K1: C = emb_h[8192,512] @ W_h[1536,512]^T + bias  (fp16 mma, NT)
// double-buffered smem, one sync per k-stage. Q stored pre-scaled by QSCALE.
// ---------------------------------------------------------------------------
#define SA 40
__global__ void __launch_bounds__(256) k1_qkv(const float* __restrict__ bias)
{
    __shared__ __half As[2][128 * SA];
    __shared__ __half Bs[2][128 * SA];

    const int tid  = threadIdx.x;
    const int warp = tid >> 5;
    const int lane = tid & 31;
    const int g = lane >> 2, t = lane & 3;
    const int wm0 = (warp >> 2) * 64;
    const int wn0 = (warp & 3) * 32;
    const int m0 = blockIdx.y * 128;
    const int n0 = blockIdx.x * 128;

    const int lrow = tid >> 1;
    const int lk   = (tid & 1) * 16;
    const __half* ap = g_Ah + (size_t)(m0 + lrow) * EMB + lk;
    const __half* bp = g_Bh + (size_t)(n0 + lrow) * EMB + lk;

    const int lm = lane & 15;
    const int lc = (lane >> 4) * 8;

    float acc[4][4][4];
#pragma unroll
    for (int i = 0; i < 4; i++)
#pragma unroll
        for (int j = 0; j < 4; j++)
#pragma unroll
            for (int c = 0; c < 4; c++) acc[i][j][c] = 0.0f;

    uint4 a0 = *(const uint4*)(ap);
    uint4 a1 = *(const uint4*)(ap + 8);
    uint4 b0 = *(const uint4*)(bp);
    uint4 b1 = *(const uint4*)(bp + 8);
    *(uint4*)(As[0] + lrow * SA + lk)     = a0;
    *(uint4*)(As[0] + lrow * SA + lk + 8) = a1;
    *(uint4*)(Bs[0] + lrow * SA + lk)     = b0;
    *(uint4*)(Bs[0] + lrow * SA + lk + 8) = b1;

#pragma unroll 4
    for (int s = 0; s < 16; s++) {
        if (s < 15) {
            const int nk = (s + 1) * 32;
            a0 = *(const uint4*)(ap + nk);
            a1 = *(const uint4*)(ap + nk + 8);
            b0 = *(const uint4*)(bp + nk);
            b1 = *(const uint4*)(bp + nk + 8);
        }
        __syncthreads();
        const __half* Ab = As[s & 1];
        const __half* Bb = Bs[s & 1];
#pragma unroll
        for (int kk = 0; kk < 32; kk += 16) {
            uint32_t af[4][4];
#pragma unroll
            for (int im = 0; im < 4; im++)
                ldsm4(af[im][0], af[im][1], af[im][2], af[im][3],
                      Ab + (wm0 + im * 16 + lm) * SA + kk + lc);
            uint32_t br0[4], br1[4];
            ldsm4(br0[0], br0[1], br0[2], br0[3], Bb + (wn0 +      lm) * SA + kk + lc);
            ldsm4(br1[0], br1[1], br1[2], br1[3], Bb + (wn0 + 16 + lm) * SA + kk + lc);
            uint32_t bf[4][2] = {{br0[0], br0[2]}, {br0[1], br0[3]},
                                 {br1[0], br1[2]}, {br1[1], br1[3]}};
#pragma unroll
            for (int im = 0; im < 4; im++)
#pragma unroll
                for (int in = 0; in < 4; in++)
                    mma_f16(acc[im][in], af[im], bf[in]);
        }
        if (s < 15) {
            __half* An = As[(s + 1) & 1];
            __half* Bn = Bs[(s + 1) & 1];
            *(uint4*)(An + lrow * SA + lk)     = a0;
            *(uint4*)(An + lrow * SA + lk + 8) = a1;
            *(uint4*)(Bn + lrow * SA + lk)     = b0;
            *(uint4*)(Bn + lrow * SA + lk + 8) = b1;
        }
    }

#pragma unroll
    for (int im = 0; im < 4; im++) {
        const int r0 = m0 + wm0 + im * 16 + g;
#pragma unroll
        for (int in = 0; in < 4; in++) {
            const int c   = n0 + wn0 + in * 8 + 2 * t;
            const int h   = c / 192;
            const int rem = c - h * 192;
            const int sect = rem >> 6;
            const int d    = rem & 63;
            const float b0f = __ldg(bias + c), b1f = __ldg(bias + c + 1);
#pragma unroll
            for (int hf = 0; hf < 2; hf++) {
                const int r = r0 + hf * 8;
                const int l = r >> 3, bb = r & 7;
                const size_t off = ((size_t)(bb * 8 + h) << 16) + l * 64 + d;
                const float v0 = acc[im][in][2 * hf    ] + b0f;
                const float v1 = acc[im][in][2 * hf + 1] + b1f;
                if (sect == 0) {
                    *(uint32_t*)(g_Q + off) = f22h2(v0 * QSCALE, v1 * QSCALE);
                } else if (sect == 1) {
                    *(uint32_t*)(g_K + off) = f22h2(v0, v1);
                } else {
                    *(float2*)(g_V + off) = make_float2(v0, v1);
                }
            }
        }
    }
}

// ---------------------------------------------------------------------------
// K2: scores (log2 domain) = Qs @ K^T per B, tile 128x128, d=64 in SMEM.
// Epilogue exps via ex2.approx.f16x2 (one MUFU op per TWO elements),
// accumulated in fp32.
// PASS2=false: Z[row] += sum over cols of exp2(S)            (row sums)
// PASS2=true : W[col] += sum over rows of exp2(S)*rcp(Z)     (col sums)
// ---------------------------------------------------------------------------
#define SQ 72
template<bool PASS2>
__global__ void __launch_bounds__(256) k2_attn()
{
    __shared__ __half Qs[128 * SQ];
    __shared__ __half Ks[128 * SQ];

    const int tid  = threadIdx.x;
    const int warp = tid >> 5;
    const int lane = tid & 31;
    const int g = lane >> 2, t = lane & 3;
    const int wm0 = (warp >> 2) * 64;
    const int wn0 = (warp & 3) * 32;

    const int B  = blockIdx.z;
    const int n0 = blockIdx.x * 128;    // keys
    const int m0 = blockIdx.y * 128;    // queries

    const __half* qg = g_Q + ((size_t)B << 16) + (size_t)m0 * 64;
    const __half* kg = g_K + ((size_t)B << 16) + (size_t)n0 * 64;

#pragma unroll
    for (int j = 0; j < 4; j++) {
        const int idx = tid + j * 256;
        const int row = idx >> 3;
        const int ch  = (idx & 7) * 8;
        *(uint4*)(Qs + row * SQ + ch) = *(const uint4*)(qg + row * 64 + ch);
        *(uint4*)(Ks + row * SQ + ch) = *(const uint4*)(kg + row * 64 + ch);
    }
    __syncthreads();

    const int lm = lane & 15;
    const int lc = (lane >> 4) * 8;

    float acc[4][4][4];
#pragma unroll
    for (int i = 0; i < 4; i++)
#pragma unroll
        for (int j = 0; j < 4; j++)
#pragma unroll
            for (int c = 0; c < 4; c++) acc[i][j][c] = 0.0f;

#pragma unroll
    for (int kk = 0; kk < 64; kk += 16) {
        uint32_t af[4][4];
#pragma unroll
        for (int im = 0; im < 4; im++)
            ldsm4(af[im][0], af[im][1], af[im][2], af[im][3],
                  Qs + (wm0 + im * 16 + lm) * SQ + kk + lc);
        uint32_t br0[4], br1[4];
        ldsm4(br0[0], br0[1], br0[2], br0[3], Ks + (wn0 +      lm) * SQ + kk + lc);
        ldsm4(br1[0], br1[1], br1[2], br1[3], Ks + (wn0 + 16 + lm) * SQ + kk + lc);
        uint32_t bf[4][2] = {{br0[0], br0[2]}, {br0[1], br0[3]},
                             {br1[0], br1[2]}, {br1[1], br1[3]}};
#pragma unroll
        for (int im = 0; im < 4; im++)
#pragma unroll
            for (int in = 0; in < 4; in++)
                mma_f16(acc[im][in], af[im], bf[in]);
    }

    if (!PASS2) {
        // row sums -> g_Z. acc[..][2h],acc[..][2h+1] are the SAME row (cols 2t,2t+1)
#pragma unroll
        for (int im = 0; im < 4; im++) {
#pragma unroll
            for (int hf = 0; hf < 2; hf++) {
                const int row = m0 + wm0 + im * 16 + g + hf * 8;
                float rp = 0.0f;
#pragma unroll
                for (int in = 0; in < 4; in++) {
                    const float2 e = ex2_pair(acc[im][in][2 * hf],
                                              acc[im][in][2 * hf + 1]);
                    rp += e.x + e.y;
                }
                rp += __shfl_xor_sync(0xffffffffu, rp, 1);
                rp += __shfl_xor_sync(0xffffffffu, rp, 2);
                if (t == 0)
                    atomicAdd(&g_Z[B * 1024 + row], rp);
            }
        }
    } else {
        // col sums of exp2 * rcp(Z[row]) -> g_W
        float ca[4][2];
#pragma unroll
        for (int in = 0; in < 4; in++) { ca[in][0] = 0.0f; ca[in][1] = 0.0f; }
#pragma unroll
        for (int im = 0; im < 4; im++) {
            const int rowg = m0 + wm0 + im * 16 + g;
            const float rA = frcp(__ldg(&g_Z[B * 1024 + rowg]));
            const float rB = frcp(__ldg(&g_Z[B * 1024 + rowg + 8]));
#pragma unroll
            for (int in = 0; in < 4; in++) {
                const float2 eA = ex2_pair(acc[im][in][0], acc[im][in][1]);
                const float2 eB = ex2_pair(acc[im][in][2], acc[im][in][3]);
                ca[in][0] = fmaf(eA.x, rA, fmaf(eB.x, rB, ca[in][0]));
                ca[in][1] = fmaf(eA.y, rA, fmaf(eB.y, rB, ca[in][1]));
            }
        }
#pragma unroll
        for (int in = 0; in < 4; in++) {
#pragma unroll
            for (int s = 0; s < 2; s++) {
                float v = ca[in][s];
                v += __shfl_xor_sync(0xffffffffu, v, 4);
                v += __shfl_xor_sync(0xffffffffu, v, 8);
                v += __shfl_xor_sync(0xffffffffu, v, 16);
                if (lane < 4)
                    atomicAdd(&g_W[B * 1024 + n0 + wn0 + in * 8 + 2 * t + s], v);
            }
        }
    }
}

// ---------------------------------------------------------------------------
// K4a: partial dot products. grid (8 chunks, 64 B), block 256.
// ---------------------------------------------------------------------------
__global__ void __launch_bounds__(256) k4a_partial()
{
    const int B  = blockIdx.y;
    const int ch = blockIdx.x;
    const int tid = threadIdx.x;
    const int d = tid & 63, mg = tid >> 6;

    const float* vptr = g_V + ((size_t)B << 16) + (size_t)ch * 128 * 64 + d;
    const float* wp   = g_W + B * 1024 + ch * 128;

    float acc = 0.0f;
#pragma unroll 8
    for (int m = mg; m < 128; m += 4)
        acc = fmaf(wp[m], vptr[m * 64], acc);

    __shared__ float sh[4][64];
    sh[mg][d] = acc;
    __syncthreads();
    if (tid < 64)
        g_P[(B * 8 + ch) * 64 + tid] =
            sh[0][tid] + sh[1][tid] + sh[2][tid] + sh[3][tid];
}

// ---------------------------------------------------------------------------
// K4b: reduce 8 partials + GroupNorm + affine + out. grid 64, block 64.
// ---------------------------------------------------------------------------
__global__ void __launch_bounds__(64) k4b_gn(
    const float* __restrict__ gw, const float* __restrict__ gb,
    float* __restrict__ out)
{
    const int B  = blockIdx.x;
    const int bb = B >> 3, hh = B & 7;
    const int tid = threadIdx.x;
    const int lane = tid & 31, wp = tid >> 5;

    float v = 0.0f;
#pragma unroll
    for (int c = 0; c < 8; c++)
        v += g_P[(B * 8 + c) * 64 + tid];

    float s = v, sq = v * v;
#pragma unroll
    for (int o = 16; o > 0; o >>= 1) {
        s  += __shfl_xor_sync(0xffffffffu, s, o);
        sq += __shfl_xor_sync(0xffffffffu, sq, o);
    }
    __shared__ float red[4];
    if (lane == 0) { red[wp * 2] = s; red[wp * 2 + 1] = sq; }
    __syncthreads();
    const float sum = red[0] + red[2];
    const float ssq = red[1] + red[3];
    const float mean = sum * (1.0f / 64.0f);
    const float var  = ssq * (1.0f / 64.0f) - mean * mean;
    out[bb * 512 + hh * 64 + tid] =
        (v - mean) * rsqrtf(var + 1e-5f) * __ldg(gw + hh) + __ldg(gb + hh);
}

// ---------------------------------------------------------------------------
// Launcher (graph-capturable)
// ---------------------------------------------------------------------------
extern "C" void kernel_launch(void* const* d_in, const int* in_sizes, int n_in,
                              void* d_out, int out_size)
{
    (void)in_sizes; (void)n_in; (void)out_size;
    const float* emb = (const float*)d_in[0];
    const float* Wq  = (const float*)d_in[1];
    const float* bq  = (const float*)d_in[2];
    const float* gw  = (const float*)d_in[3];
    const float* gb  = (const float*)d_in[4];
    float* out = (float*)d_out;

    kcvt     <<<1216, 1024>>>(emb, Wq);
    k1_qkv   <<<dim3(12, 64), 256>>>(bq);
    k2_attn<false><<<dim3(8, 8, 64), 256>>>();
    k2_attn<true> <<<dim3(8, 8, 64), 256>>>();
    k4a_partial<<<dim3(8, 64), 256>>>();
    k4b_gn   <<<64, 64>>>(gw, gb, out);
}

// round 13
// speedup vs baseline: 1.3573x; 1.0817x over previous
#include <cuda_runtime.h>
#include <cuda_fp16.h>
#include <cstdint>

#define L_SEQ 1024
#define BATCH_BS 8
#define EMB 512
#define O3 1536
#define NB 64            // BATCH_BS * NH

// Q pre-scale: exp(0.125*s) = exp2(s * 0.125 * log2(e))
#define QSCALE 0.18033688011112042f

// Scratch (device globals)
__device__ __half g_Ah[(size_t)8192 * EMB];       // emb as fp16, 8 MB
__device__ __half g_Bh[(size_t)O3 * EMB];         // W_qkv as fp16, 1.5 MB
__device__ __half g_Q[(size_t)NB * L_SEQ * 64];   // 8 MB (pre-scaled by QSCALE)
__device__ __half g_K[(size_t)NB * L_SEQ * 64];   // 8 MB
__device__ float  g_V[(size_t)NB * L_SEQ * 64];   // 16 MB
__device__ float  g_Z[NB * L_SEQ];                // raw row sums (atomic)
__device__ float  g_W[NB * L_SEQ];                // attn weights (atomic)
__device__ float  g_P[NB * 8 * 64];               // k4a partials

// ---------------------------------------------------------------------------
// helpers
// ---------------------------------------------------------------------------
__device__ __forceinline__ uint32_t f22h2(float lo, float hi) {
    __half2 h = __floats2half2_rn(lo, hi);
    return reinterpret_cast<uint32_t&>(h);
}
__device__ __forceinline__ uint32_t smem_u32(const void* p) {
    return (uint32_t)__cvta_generic_to_shared(p);
}
__device__ __forceinline__ float frcp(float x) {
    float r;
    asm("rcp.approx.f32 %0, %1;" : "=f"(r) : "f"(x));
    return r;
}
// pack two fp32 -> fp16x2, exp2 both with ONE MUFU op; result stays packed
__device__ __forceinline__ uint32_t ex2h2(float a, float b) {
    uint32_t p = f22h2(a, b), e;
    asm("ex2.approx.f16x2 %0, %1;" : "=r"(e) : "r"(p));
    return e;
}
__device__ __forceinline__ uint32_t hmul2u(uint32_t a, uint32_t b) {
    uint32_t r;
    asm("mul.f16x2 %0, %1, %2;" : "=r"(r) : "r"(a), "r"(b));
    return r;
}
__device__ __forceinline__ void ldsm4(uint32_t& r0, uint32_t& r1,
                                      uint32_t& r2, uint32_t& r3,
                                      const __half* p) {
    uint32_t addr = smem_u32(p);
    asm volatile("ldmatrix.sync.aligned.m8n8.x4.shared.b16 {%0,%1,%2,%3}, [%4];"
                 : "=r"(r0), "=r"(r1), "=r"(r2), "=r"(r3) : "r"(addr));
}
__device__ __forceinline__ void mma_f16(float* d, const uint32_t* a, const uint32_t* b) {
    asm volatile(
        "mma.sync.aligned.m16n8k16.row.col.f32.f16.f16.f32 "
        "{%0,%1,%2,%3}, {%4,%5,%6,%7}, {%8,%9}, {%0,%1,%2,%3};\n"
        : "+f"(d[0]), "+f"(d[1]), "+f"(d[2]), "+f"(d[3])
        : "r"(a[0]), "r"(a[1]), "r"(a[2]), "r"(a[3]), "r"(b[0]), "r"(b[1]));
}

// ---------------------------------------------------------------------------
// KC: one-time fp32 -> fp16 convert of emb + W_qkv; zero Z and W.
// ---------------------------------------------------------------------------
__global__ void __launch_bounds__(1024) kcvt(
    const float* __restrict__ A, const float* __restrict__ B)
{
    const size_t i = (size_t)blockIdx.x * 1024 + threadIdx.x;
    if (i < 1048576) {
        const float4 v = ((const float4*)A)[i];
        ((uint2*)g_Ah)[i] = make_uint2(f22h2(v.x, v.y), f22h2(v.z, v.w));
    } else {
        const size_t j = i - 1048576;
        const float4 v = ((const float4*)B)[j];
        ((uint2*)g_Bh)[j] = make_uint2(f22h2(v.x, v.y), f22h2(v.z, v.w));
    }
    if (i < NB * L_SEQ) {
        g_Z[i] = 0.0f;
        g_W[i] = 0.0f;
    }
}

// ---------------------------------------------------------------------------
// K1: C = emb_h[8192,512] @ W_h[1536,512]^T + bias  (fp16 mma, NT)
// double-buffered smem, one sync per k-stage. Q stored pre-scaled by QSCALE.
// ---------------------------------------------------------------------------
#define SA 40
__global__ void __launch_bounds__(256) k1_qkv(const float* __restrict__ bias)
{
    __shared__ __half As[2][128 * SA];
    __shared__ __half Bs[2][128 * SA];

    const int tid  = threadIdx.x;
    const int warp = tid >> 5;
    const int lane = tid & 31;
    const int g = lane >> 2, t = lane & 3;
    const int wm0 = (warp >> 2) * 64;
    const int wn0 = (warp & 3) * 32;
    const int m0 = blockIdx.y * 128;
    const int n0 = blockIdx.x * 128;

    const int lrow = tid >> 1;
    const int lk   = (tid & 1) * 16;
    const __half* ap = g_Ah + (size_t)(m0 + lrow) * EMB + lk;
    const __half* bp = g_Bh + (size_t)(n0 + lrow) * EMB + lk;

    const int lm = lane & 15;
    const int lc = (lane >> 4) * 8;

    float acc[4][4][4];
#pragma unroll
    for (int i = 0; i < 4; i++)
#pragma unroll
        for (int j = 0; j < 4; j++)
#pragma unroll
            for (int c = 0; c < 4; c++) acc[i][j][c] = 0.0f;

    uint4 a0 = *(const uint4*)(ap);
    uint4 a1 = *(const uint4*)(ap + 8);
    uint4 b0 = *(const uint4*)(bp);
    uint4 b1 = *(const uint4*)(bp + 8);
    *(uint4*)(As[0] + lrow * SA + lk)     = a0;
    *(uint4*)(As[0] + lrow * SA + lk + 8) = a1;
    *(uint4*)(Bs[0] + lrow * SA + lk)     = b0;
    *(uint4*)(Bs[0] + lrow * SA + lk + 8) = b1;

#pragma unroll 4
    for (int s = 0; s < 16; s++) {
        if (s < 15) {
            const int nk = (s + 1) * 32;
            a0 = *(const uint4*)(ap + nk);
            a1 = *(const uint4*)(ap + nk + 8);
            b0 = *(const uint4*)(bp + nk);
            b1 = *(const uint4*)(bp + nk + 8);
        }
        __syncthreads();
        const __half* Ab = As[s & 1];
        const __half* Bb = Bs[s & 1];
#pragma unroll
        for (int kk = 0; kk < 32; kk += 16) {
            uint32_t af[4][4];
#pragma unroll
            for (int im = 0; im < 4; im++)
                ldsm4(af[im][0], af[im][1], af[im][2], af[im][3],
                      Ab + (wm0 + im * 16 + lm) * SA + kk + lc);
            uint32_t br0[4], br1[4];
            ldsm4(br0[0], br0[1], br0[2], br0[3], Bb + (wn0 +      lm) * SA + kk + lc);
            ldsm4(br1[0], br1[1], br1[2], br1[3], Bb + (wn0 + 16 + lm) * SA + kk + lc);
            uint32_t bf[4][2] = {{br0[0], br0[2]}, {br0[1], br0[3]},
                                 {br1[0], br1[2]}, {br1[1], br1[3]}};
#pragma unroll
            for (int im = 0; im < 4; im++)
#pragma unroll
                for (int in = 0; in < 4; in++)
                    mma_f16(acc[im][in], af[im], bf[in]);
        }
        if (s < 15) {
            __half* An = As[(s + 1) & 1];
            __half* Bn = Bs[(s + 1) & 1];
            *(uint4*)(An + lrow * SA + lk)     = a0;
            *(uint4*)(An + lrow * SA + lk + 8) = a1;
            *(uint4*)(Bn + lrow * SA + lk)     = b0;
            *(uint4*)(Bn + lrow * SA + lk + 8) = b1;
        }
    }

#pragma unroll
    for (int im = 0; im < 4; im++) {
        const int r0 = m0 + wm0 + im * 16 + g;
#pragma unroll
        for (int in = 0; in < 4; in++) {
            const int c   = n0 + wn0 + in * 8 + 2 * t;
            const int h   = c / 192;
            const int rem = c - h * 192;
            const int sect = rem >> 6;
            const int d    = rem & 63;
            const float b0f = __ldg(bias + c), b1f = __ldg(bias + c + 1);
#pragma unroll
            for (int hf = 0; hf < 2; hf++) {
                const int r = r0 + hf * 8;
                const int l = r >> 3, bb = r & 7;
                const size_t off = ((size_t)(bb * 8 + h) << 16) + l * 64 + d;
                const float v0 = acc[im][in][2 * hf    ] + b0f;
                const float v1 = acc[im][in][2 * hf + 1] + b1f;
                if (sect == 0) {
                    *(uint32_t*)(g_Q + off) = f22h2(v0 * QSCALE, v1 * QSCALE);
                } else if (sect == 1) {
                    *(uint32_t*)(g_K + off) = f22h2(v0, v1);
                } else {
                    *(float2*)(g_V + off) = make_float2(v0, v1);
                }
            }
        }
    }
}

// ---------------------------------------------------------------------------
// K2: scores (log2 domain) per B, tile 128x128, d=64 in SMEM.
// PASS1 (PASS2=false): S = Q @ K^T; Z[row] += rowsum(exp2 S) via ones-mma.
// PASS2 (PASS2=true) : S' = K @ Q^T (transposed scores); queries are the
//   t-paired column dim, so W[key] += rowsum(exp2(S') * r[query]) is again a
//   ones-mma row reduction after one HMUL2 per packed pair.
// Epilogue: ex2.approx.f16x2 keeps E packed as native m16n8k16 A-fragments;
// reductions run on the tensor pipe (2 mmas per im), extraction by t==0 lanes.
// ---------------------------------------------------------------------------
#define SQ 72
template<bool PASS2>
__global__ void __launch_bounds__(256) k2_attn()
{
    __shared__ __half Qs[128 * SQ];
    __shared__ __half Ks[128 * SQ];
    __shared__ float  rsh[128];

    const int tid  = threadIdx.x;
    const int warp = tid >> 5;
    const int lane = tid & 31;
    const int g = lane >> 2, t = lane & 3;
    const int wm0 = (warp >> 2) * 64;
    const int wn0 = (warp & 3) * 32;

    const int B  = blockIdx.z;
    const int n0 = blockIdx.x * 128;    // keys
    const int m0 = blockIdx.y * 128;    // queries

    const __half* qg = g_Q + ((size_t)B << 16) + (size_t)m0 * 64;
    const __half* kg = g_K + ((size_t)B << 16) + (size_t)n0 * 64;

#pragma unroll
    for (int j = 0; j < 4; j++) {
        const int idx = tid + j * 256;
        const int row = idx >> 3;
        const int ch  = (idx & 7) * 8;
        *(uint4*)(Qs + row * SQ + ch) = *(const uint4*)(qg + row * 64 + ch);
        *(uint4*)(Ks + row * SQ + ch) = *(const uint4*)(kg + row * 64 + ch);
    }
    if (PASS2 && tid < 128)
        rsh[tid] = frcp(g_Z[B * 1024 + m0 + tid]);
    __syncthreads();

    // operand roles: PASS1 A=Q,B=K (rows=queries); PASS2 A=K,B=Q (rows=keys)
    const __half* At = PASS2 ? Ks : Qs;
    const __half* Bt = PASS2 ? Qs : Ks;

    const int lm = lane & 15;
    const int lc = (lane >> 4) * 8;

    float acc[4][4][4];
#pragma unroll
    for (int i = 0; i < 4; i++)
#pragma unroll
        for (int j = 0; j < 4; j++)
#pragma unroll
            for (int c = 0; c < 4; c++) acc[i][j][c] = 0.0f;

#pragma unroll
    for (int kk = 0; kk < 64; kk += 16) {
        uint32_t af[4][4];
#pragma unroll
        for (int im = 0; im < 4; im++)
            ldsm4(af[im][0], af[im][1], af[im][2], af[im][3],
                  At + (wm0 + im * 16 + lm) * SQ + kk + lc);
        uint32_t br0[4], br1[4];
        ldsm4(br0[0], br0[1], br0[2], br0[3], Bt + (wn0 +      lm) * SQ + kk + lc);
        ldsm4(br1[0], br1[1], br1[2], br1[3], Bt + (wn0 + 16 + lm) * SQ + kk + lc);
        uint32_t bf[4][2] = {{br0[0], br0[2]}, {br0[1], br0[3]},
                             {br1[0], br1[2]}, {br1[1], br1[3]}};
#pragma unroll
        for (int im = 0; im < 4; im++)
#pragma unroll
            for (int in = 0; in < 4; in++)
                mma_f16(acc[im][in], af[im], bf[in]);
    }

    // --- epilogue: packed exp2, optional r-scale, ones-mma row reduction ---
    // eh[im][in][0] = E(row g,   cols 2t,2t+1) ; eh[im][in][1] = row g+8
    uint32_t eh[4][4][2];
#pragma unroll
    for (int im = 0; im < 4; im++)
#pragma unroll
        for (int in = 0; in < 4; in++) {
            eh[im][in][0] = ex2h2(acc[im][in][0], acc[im][in][1]);
            eh[im][in][1] = ex2h2(acc[im][in][2], acc[im][in][3]);
        }

    if (PASS2) {
        // scale packed pairs by r of the query columns (same for both rows)
#pragma unroll
        for (int in = 0; in < 4; in++) {
            const int cl = wn0 + in * 8 + 2 * t;
            const uint32_t rq = f22h2(rsh[cl], rsh[cl + 1]);
#pragma unroll
            for (int im = 0; im < 4; im++) {
                eh[im][in][0] = hmul2u(eh[im][in][0], rq);
                eh[im][in][1] = hmul2u(eh[im][in][1], rq);
            }
        }
    }

    const uint32_t ones2 = 0x3C003C00u;   // h2(1.0, 1.0)
    uint32_t bones[2] = {ones2, ones2};
    float* target = PASS2 ? g_W : g_Z;
    const int rbase = (PASS2 ? n0 : m0) + wm0;

#pragma unroll
    for (int im = 0; im < 4; im++) {
        float rs[4] = {0.0f, 0.0f, 0.0f, 0.0f};
        uint32_t afr0[4] = {eh[im][0][0], eh[im][0][1], eh[im][1][0], eh[im][1][1]};
        mma_f16(rs, afr0, bones);
        uint32_t afr1[4] = {eh[im][2][0], eh[im][2][1], eh[im][3][0], eh[im][3][1]};
        mma_f16(rs, afr1, bones);
        if (t == 0) {
            const int row = rbase + im * 16 + g;
            atomicAdd(&target[B * 1024 + row],     rs[0]);
            atomicAdd(&target[B * 1024 + row + 8], rs[2]);
        }
    }
}

// ---------------------------------------------------------------------------
// K4a: partial dot products. grid (8 chunks, 64 B), block 256.
// ---------------------------------------------------------------------------
__global__ void __launch_bounds__(256) k4a_partial()
{
    const int B  = blockIdx.y;
    const int ch = blockIdx.x;
    const int tid = threadIdx.x;
    const int d = tid & 63, mg = tid >> 6;

    const float* vptr = g_V + ((size_t)B << 16) + (size_t)ch * 128 * 64 + d;
    const float* wp   = g_W + B * 1024 + ch * 128;

    float acc = 0.0f;
#pragma unroll 8
    for (int m = mg; m < 128; m += 4)
        acc = fmaf(wp[m], vptr[m * 64], acc);

    __shared__ float sh[4][64];
    sh[mg][d] = acc;
    __syncthreads();
    if (tid < 64)
        g_P[(B * 8 + ch) * 64 + tid] =
            sh[0][tid] + sh[1][tid] + sh[2][tid] + sh[3][tid];
}

// ---------------------------------------------------------------------------
// K4b: reduce 8 partials + GroupNorm + affine + out. grid 64, block 64.
// ---------------------------------------------------------------------------
__global__ void __launch_bounds__(64) k4b_gn(
    const float* __restrict__ gw, const float* __restrict__ gb,
    float* __restrict__ out)
{
    const int B  = blockIdx.x;
    const int bb = B >> 3, hh = B & 7;
    const int tid = threadIdx.x;
    const int lane = tid & 31, wp = tid >> 5;

    float v = 0.0f;
#pragma unroll
    for (int c = 0; c < 8; c++)
        v += g_P[(B * 8 + c) * 64 + tid];

    float s = v, sq = v * v;
#pragma unroll
    for (int o = 16; o > 0; o >>= 1) {
        s  += __shfl_xor_sync(0xffffffffu, s, o);
        sq += __shfl_xor_sync(0xffffffffu, sq, o);
    }
    __shared__ float red[4];
    if (lane == 0) { red[wp * 2] = s; red[wp * 2 + 1] = sq; }
    __syncthreads();
    const float sum = red[0] + red[2];
    const float ssq = red[1] + red[3];
    const float mean = sum * (1.0f / 64.0f);
    const float var  = ssq * (1.0f / 64.0f) - mean * mean;
    out[bb * 512 + hh * 64 + tid] =
        (v - mean) * rsqrtf(var + 1e-5f) * __ldg(gw + hh) + __ldg(gb + hh);
}

// ---------------------------------------------------------------------------
// Launcher (graph-capturable)
// ---------------------------------------------------------------------------
extern "C" void kernel_launch(void* const* d_in, const int* in_sizes, int n_in,
                              void* d_out, int out_size)
{
    (void)in_sizes; (void)n_in; (void)out_size;
    const float* emb = (const float*)d_in[0];
    const float* Wq  = (const float*)d_in[1];
    const float* bq  = (const float*)d_in[2];
    const float* gw  = (const float*)d_in[3];
    const float* gb  = (const float*)d_in[4];
    float* out = (float*)d_out;

    kcvt     <<<1216, 1024>>>(emb, Wq);
    k1_qkv   <<<dim3(12, 64), 256>>>(bq);
    k2_attn<false><<<dim3(8, 8, 64), 256>>>();
    k2_attn<true> <<<dim3(8, 8, 64), 256>>>();
    k4a_partial<<<dim3(8, 64), 256>>>();
    k4b_gn   <<<64, 64>>>(gw, gb, out);
}

// round 14
// speedup vs baseline: 1.3753x; 1.0133x over previous
#include <cuda_runtime.h>
#include <cuda_fp16.h>
#include <cstdint>

#define L_SEQ 1024
#define BATCH_BS 8
#define EMB 512
#define O3 1536
#define NB 64            // BATCH_BS * NH

// Q pre-scale: exp(0.125*s) = exp2(s * 0.125 * log2(e))
#define QSCALE 0.18033688011112042f

// Scratch (device globals)
__device__ __half g_Ah[(size_t)8192 * EMB];       // emb as fp16, 8 MB
__device__ __half g_Bh[(size_t)O3 * EMB];         // W_qkv as fp16, 1.5 MB
__device__ __half g_Q[(size_t)NB * L_SEQ * 64];   // 8 MB (pre-scaled by QSCALE)
__device__ __half g_K[(size_t)NB * L_SEQ * 64];   // 8 MB
__device__ float  g_V[(size_t)NB * L_SEQ * 64];   // 16 MB
__device__ float  g_Z[NB * L_SEQ];                // raw row sums (atomic)
__device__ float  g_W[NB * L_SEQ];                // attn weights (atomic)
__device__ float  g_P[NB * 8 * 64];               // k4a partials

// ---------------------------------------------------------------------------
// helpers
// ---------------------------------------------------------------------------
__device__ __forceinline__ uint32_t f22h2(float lo, float hi) {
    __half2 h = __floats2half2_rn(lo, hi);
    return reinterpret_cast<uint32_t&>(h);
}
__device__ __forceinline__ uint32_t smem_u32(const void* p) {
    return (uint32_t)__cvta_generic_to_shared(p);
}
__device__ __forceinline__ float frcp(float x) {
    float r;
    asm("rcp.approx.f32 %0, %1;" : "=f"(r) : "f"(x));
    return r;
}
// pack two fp32 -> fp16x2, exp2 both with ONE MUFU op; result stays packed
__device__ __forceinline__ uint32_t ex2h2(float a, float b) {
    uint32_t p = f22h2(a, b), e;
    asm("ex2.approx.f16x2 %0, %1;" : "=r"(e) : "r"(p));
    return e;
}
__device__ __forceinline__ void ldsm4(uint32_t& r0, uint32_t& r1,
                                      uint32_t& r2, uint32_t& r3,
                                      const __half* p) {
    uint32_t addr = smem_u32(p);
    asm volatile("ldmatrix.sync.aligned.m8n8.x4.shared.b16 {%0,%1,%2,%3}, [%4];"
                 : "=r"(r0), "=r"(r1), "=r"(r2), "=r"(r3) : "r"(addr));
}
__device__ __forceinline__ void mma_f16(float* d, const uint32_t* a, const uint32_t* b) {
    asm volatile(
        "mma.sync.aligned.m16n8k16.row.col.f32.f16.f16.f32 "
        "{%0,%1,%2,%3}, {%4,%5,%6,%7}, {%8,%9}, {%0,%1,%2,%3};\n"
        : "+f"(d[0]), "+f"(d[1]), "+f"(d[2]), "+f"(d[3])
        : "r"(a[0]), "r"(a[1]), "r"(a[2]), "r"(a[3]), "r"(b[0]), "r"(b[1]));
}

// ---------------------------------------------------------------------------
// KC: one-time fp32 -> fp16 convert of emb + W_qkv; zero Z and W.
// ---------------------------------------------------------------------------
__global__ void __launch_bounds__(1024) kcvt(
    const float* __restrict__ A, const float* __restrict__ B)
{
    const size_t i = (size_t)blockIdx.x * 1024 + threadIdx.x;
    if (i < 1048576) {
        const float4 v = ((const float4*)A)[i];
        ((uint2*)g_Ah)[i] = make_uint2(f22h2(v.x, v.y), f22h2(v.z, v.w));
    } else {
        const size_t j = i - 1048576;
        const float4 v = ((const float4*)B)[j];
        ((uint2*)g_Bh)[j] = make_uint2(f22h2(v.x, v.y), f22h2(v.z, v.w));
    }
    if (i < NB * L_SEQ) {
        g_Z[i] = 0.0f;
        g_W[i] = 0.0f;
    }
}

// ---------------------------------------------------------------------------
// K1: C = emb_h[8192,512] @ W_h[1536,512]^T + bias  (fp16 mma, NT)
// double-buffered smem, one sync per k-stage. Q stored pre-scaled by QSCALE.
// ---------------------------------------------------------------------------
#define SA 40
__global__ void __launch_bounds__(256) k1_qkv(const float* __restrict__ bias)
{
    __shared__ __half As[2][128 * SA];
    __shared__ __half Bs[2][128 * SA];

    const int tid  = threadIdx.x;
    const int warp = tid >> 5;
    const int lane = tid & 31;
    const int g = lane >> 2, t = lane & 3;
    const int wm0 = (warp >> 2) * 64;
    const int wn0 = (warp & 3) * 32;
    const int m0 = blockIdx.y * 128;
    const int n0 = blockIdx.x * 128;

    const int lrow = tid >> 1;
    const int lk   = (tid & 1) * 16;
    const __half* ap = g_Ah + (size_t)(m0 + lrow) * EMB + lk;
    const __half* bp = g_Bh + (size_t)(n0 + lrow) * EMB + lk;

    const int lm = lane & 15;
    const int lc = (lane >> 4) * 8;

    float acc[4][4][4];
#pragma unroll
    for (int i = 0; i < 4; i++)
#pragma unroll
        for (int j = 0; j < 4; j++)
#pragma unroll
            for (int c = 0; c < 4; c++) acc[i][j][c] = 0.0f;

    uint4 a0 = *(const uint4*)(ap);
    uint4 a1 = *(const uint4*)(ap + 8);
    uint4 b0 = *(const uint4*)(bp);
    uint4 b1 = *(const uint4*)(bp + 8);
    *(uint4*)(As[0] + lrow * SA + lk)     = a0;
    *(uint4*)(As[0] + lrow * SA + lk + 8) = a1;
    *(uint4*)(Bs[0] + lrow * SA + lk)     = b0;
    *(uint4*)(Bs[0] + lrow * SA + lk + 8) = b1;

#pragma unroll 4
    for (int s = 0; s < 16; s++) {
        if (s < 15) {
            const int nk = (s + 1) * 32;
            a0 = *(const uint4*)(ap + nk);
            a1 = *(const uint4*)(ap + nk + 8);
            b0 = *(const uint4*)(bp + nk);
            b1 = *(const uint4*)(bp + nk + 8);
        }
        __syncthreads();
        const __half* Ab = As[s & 1];
        const __half* Bb = Bs[s & 1];
#pragma unroll
        for (int kk = 0; kk < 32; kk += 16) {
            uint32_t af[4][4];
#pragma unroll
            for (int im = 0; im < 4; im++)
                ldsm4(af[im][0], af[im][1], af[im][2], af[im][3],
                      Ab + (wm0 + im * 16 + lm) * SA + kk + lc);
            uint32_t br0[4], br1[4];
            ldsm4(br0[0], br0[1], br0[2], br0[3], Bb + (wn0 +      lm) * SA + kk + lc);
            ldsm4(br1[0], br1[1], br1[2], br1[3], Bb + (wn0 + 16 + lm) * SA + kk + lc);
            uint32_t bf[4][2] = {{br0[0], br0[2]}, {br0[1], br0[3]},
                                 {br1[0], br1[2]}, {br1[1], br1[3]}};
#pragma unroll
            for (int im = 0; im < 4; im++)
#pragma unroll
                for (int in = 0; in < 4; in++)
                    mma_f16(acc[im][in], af[im], bf[in]);
        }
        if (s < 15) {
            __half* An = As[(s + 1) & 1];
            __half* Bn = Bs[(s + 1) & 1];
            *(uint4*)(An + lrow * SA + lk)     = a0;
            *(uint4*)(An + lrow * SA + lk + 8) = a1;
            *(uint4*)(Bn + lrow * SA + lk)     = b0;
            *(uint4*)(Bn + lrow * SA + lk + 8) = b1;
        }
    }

#pragma unroll
    for (int im = 0; im < 4; im++) {
        const int r0 = m0 + wm0 + im * 16 + g;
#pragma unroll
        for (int in = 0; in < 4; in++) {
            const int c   = n0 + wn0 + in * 8 + 2 * t;
            const int h   = c / 192;
            const int rem = c - h * 192;
            const int sect = rem >> 6;
            const int d    = rem & 63;
            const float b0f = __ldg(bias + c), b1f = __ldg(bias + c + 1);
#pragma unroll
            for (int hf = 0; hf < 2; hf++) {
                const int r = r0 + hf * 8;
                const int l = r >> 3, bb = r & 7;
                const size_t off = ((size_t)(bb * 8 + h) << 16) + l * 64 + d;
                const float v0 = acc[im][in][2 * hf    ] + b0f;
                const float v1 = acc[im][in][2 * hf + 1] + b1f;
                if (sect == 0) {
                    *(uint32_t*)(g_Q + off) = f22h2(v0 * QSCALE, v1 * QSCALE);
                } else if (sect == 1) {
                    *(uint32_t*)(g_K + off) = f22h2(v0, v1);
                } else {
                    *(float2*)(g_V + off) = make_float2(v0, v1);
                }
            }
        }
    }
}

// ---------------------------------------------------------------------------
// K2: scores (log2 domain) per B, tile 128x128, d=64 in SMEM.
// PASS1: S = Q @ K^T; Z[row] += rowsum(exp2 S) via ones-mma.
// PASS2: S' = K @ Q^T; W[key] += Σ_query exp2(S') * rZ[query] via a reduce-mma
//   whose B fragment CARRIES rZ (every B column = rZ vector), so the weighted
//   reduction happens inside the tensor op — no per-element HMUL2 scaling.
// ---------------------------------------------------------------------------
#define SQ 72
template<bool PASS2>
__global__ void __launch_bounds__(256) k2_attn()
{
    __shared__ __half Qs[128 * SQ];
    __shared__ __half Ks[128 * SQ];
    __shared__ float  rsh[128];

    const int tid  = threadIdx.x;
    const int warp = tid >> 5;
    const int lane = tid & 31;
    const int g = lane >> 2, t = lane & 3;
    const int wm0 = (warp >> 2) * 64;
    const int wn0 = (warp & 3) * 32;

    const int B  = blockIdx.z;
    const int n0 = blockIdx.x * 128;    // keys
    const int m0 = blockIdx.y * 128;    // queries

    const __half* qg = g_Q + ((size_t)B << 16) + (size_t)m0 * 64;
    const __half* kg = g_K + ((size_t)B << 16) + (size_t)n0 * 64;

#pragma unroll
    for (int j = 0; j < 4; j++) {
        const int idx = tid + j * 256;
        const int row = idx >> 3;
        const int ch  = (idx & 7) * 8;
        *(uint4*)(Qs + row * SQ + ch) = *(const uint4*)(qg + row * 64 + ch);
        *(uint4*)(Ks + row * SQ + ch) = *(const uint4*)(kg + row * 64 + ch);
    }
    if (PASS2 && tid < 128)
        rsh[tid] = frcp(g_Z[B * 1024 + m0 + tid]);
    __syncthreads();

    // operand roles: PASS1 A=Q,B=K (rows=queries); PASS2 A=K,B=Q (rows=keys)
    const __half* At = PASS2 ? Ks : Qs;
    const __half* Bt = PASS2 ? Qs : Ks;

    const int lm = lane & 15;
    const int lc = (lane >> 4) * 8;

    float acc[4][4][4];
#pragma unroll
    for (int i = 0; i < 4; i++)
#pragma unroll
        for (int j = 0; j < 4; j++)
#pragma unroll
            for (int c = 0; c < 4; c++) acc[i][j][c] = 0.0f;

#pragma unroll
    for (int kk = 0; kk < 64; kk += 16) {
        uint32_t af[4][4];
#pragma unroll
        for (int im = 0; im < 4; im++)
            ldsm4(af[im][0], af[im][1], af[im][2], af[im][3],
                  At + (wm0 + im * 16 + lm) * SQ + kk + lc);
        uint32_t br0[4], br1[4];
        ldsm4(br0[0], br0[1], br0[2], br0[3], Bt + (wn0 +      lm) * SQ + kk + lc);
        ldsm4(br1[0], br1[1], br1[2], br1[3], Bt + (wn0 + 16 + lm) * SQ + kk + lc);
        uint32_t bf[4][2] = {{br0[0], br0[2]}, {br0[1], br0[3]},
                             {br1[0], br1[2]}, {br1[1], br1[3]}};
#pragma unroll
        for (int im = 0; im < 4; im++)
#pragma unroll
            for (int in = 0; in < 4; in++)
                mma_f16(acc[im][in], af[im], bf[in]);
    }

    // --- epilogue: packed exp2 -> reduce-mma (B = ones or rZ) ---
    uint32_t eh[4][4][2];
#pragma unroll
    for (int im = 0; im < 4; im++)
#pragma unroll
        for (int in = 0; in < 4; in++) {
            eh[im][in][0] = ex2h2(acc[im][in][0], acc[im][in][1]);
            eh[im][in][1] = ex2h2(acc[im][in][2], acc[im][in][3]);
        }

    // B fragments for the two reduce mmas (k = 16 queries each).
    // PASS1: all-ones. PASS2: B[k,n] = rZ[query k] for every n.
    const uint32_t ones2 = 0x3C003C00u;
    uint32_t bz0[2] = {ones2, ones2};
    uint32_t bz1[2] = {ones2, ones2};
    if (PASS2) {
        const int qb = wn0 + 2 * t;
        bz0[0] = f22h2(rsh[qb],      rsh[qb + 1]);
        bz0[1] = f22h2(rsh[qb + 8],  rsh[qb + 9]);
        bz1[0] = f22h2(rsh[qb + 16], rsh[qb + 17]);
        bz1[1] = f22h2(rsh[qb + 24], rsh[qb + 25]);
    }

    float* target = PASS2 ? g_W : g_Z;
    const int rbase = (PASS2 ? n0 : m0) + wm0;

#pragma unroll
    for (int im = 0; im < 4; im++) {
        float rs[4] = {0.0f, 0.0f, 0.0f, 0.0f};
        uint32_t afr0[4] = {eh[im][0][0], eh[im][0][1], eh[im][1][0], eh[im][1][1]};
        mma_f16(rs, afr0, bz0);
        uint32_t afr1[4] = {eh[im][2][0], eh[im][2][1], eh[im][3][0], eh[im][3][1]};
        mma_f16(rs, afr1, bz1);
        if (t == 0) {
            const int row = rbase + im * 16 + g;
            atomicAdd(&target[B * 1024 + row],     rs[0]);
            atomicAdd(&target[B * 1024 + row + 8], rs[2]);
        }
    }
}

// ---------------------------------------------------------------------------
// K4a: partial dot products. grid (8 chunks, 64 B), block 256.
// ---------------------------------------------------------------------------
__global__ void __launch_bounds__(256) k4a_partial()
{
    const int B  = blockIdx.y;
    const int ch = blockIdx.x;
    const int tid = threadIdx.x;
    const int d = tid & 63, mg = tid >> 6;

    const float* vptr = g_V + ((size_t)B << 16) + (size_t)ch * 128 * 64 + d;
    const float* wp   = g_W + B * 1024 + ch * 128;

    float acc = 0.0f;
#pragma unroll 8
    for (int m = mg; m < 128; m += 4)
        acc = fmaf(wp[m], vptr[m * 64], acc);

    __shared__ float sh[4][64];
    sh[mg][d] = acc;
    __syncthreads();
    if (tid < 64)
        g_P[(B * 8 + ch) * 64 + tid] =
            sh[0][tid] + sh[1][tid] + sh[2][tid] + sh[3][tid];
}

// ---------------------------------------------------------------------------
// K4b: reduce 8 partials + GroupNorm + affine + out. grid 64, block 64.
// ---------------------------------------------------------------------------
__global__ void __launch_bounds__(64) k4b_gn(
    const float* __restrict__ gw, const float* __restrict__ gb,
    float* __restrict__ out)
{
    const int B  = blockIdx.x;
    const int bb = B >> 3, hh = B & 7;
    const int tid = threadIdx.x;
    const int lane = tid & 31, wp = tid >> 5;

    float v = 0.0f;
#pragma unroll
    for (int c = 0; c < 8; c++)
        v += g_P[(B * 8 + c) * 64 + tid];

    float s = v, sq = v * v;
#pragma unroll
    for (int o = 16; o > 0; o >>= 1) {
        s  += __shfl_xor_sync(0xffffffffu, s, o);
        sq += __shfl_xor_sync(0xffffffffu, sq, o);
    }
    __shared__ float red[4];
    if (lane == 0) { red[wp * 2] = s; red[wp * 2 + 1] = sq; }
    __syncthreads();
    const float sum = red[0] + red[2];
    const float ssq = red[1] + red[3];
    const float mean = sum * (1.0f / 64.0f);
    const float var  = ssq * (1.0f / 64.0f) - mean * mean;
    out[bb * 512 + hh * 64 + tid] =
        (v - mean) * rsqrtf(var + 1e-5f) * __ldg(gw + hh) + __ldg(gb + hh);
}

// ---------------------------------------------------------------------------
// Launcher (graph-capturable)
// ---------------------------------------------------------------------------
extern "C" void kernel_launch(void* const* d_in, const int* in_sizes, int n_in,
                              void* d_out, int out_size)
{
    (void)in_sizes; (void)n_in; (void)out_size;
    const float* emb = (const float*)d_in[0];
    const float* Wq  = (const float*)d_in[1];
    const float* bq  = (const float*)d_in[2];
    const float* gw  = (const float*)d_in[3];
    const float* gb  = (const float*)d_in[4];
    float* out = (float*)d_out;

    kcvt     <<<1216, 1024>>>(emb, Wq);
    k1_qkv   <<<dim3(12, 64), 256>>>(bq);
    k2_attn<false><<<dim3(8, 8, 64), 256>>>();
    k2_attn<true> <<<dim3(8, 8, 64), 256>>>();
    k4a_partial<<<dim3(8, 64), 256>>>();
    k4b_gn   <<<64, 64>>>(gw, gb, out);
}